// round 8
// baseline (speedup 1.0000x reference)
#include <cuda_runtime.h>
#include <cuda_bf16.h>

#define BB      8192
#define FF      2048
#define NRULES  512
#define GG      16
#define NPAIR   136          // upper triangle incl. diagonal of 16x16
#define NSTAT   152          // 16 sums + 136 pair-products
#define CHUNKS  4
#define RPC     (BB / CHUNKS)   // 2048 rows per chunk
#define EPSV    1e-5f
#define FULLMASK 0xffffffffu

// Scratch (device globals: allocation-free per harness rules)
__device__ float g_xT[(size_t)FF * BB];            // 64MB transposed x
__device__ float g_stats[NRULES][CHUNKS][NSTAT];   // partial moments
__device__ __align__(16) float g_wF[FF];           // folded GEMV weights
__device__ float g_c0;                             // folded constant

// ---------------------------------------------------------------------------
// packed f32x2 helpers (sm_103a)
// ---------------------------------------------------------------------------
__device__ __forceinline__ unsigned long long fma2(unsigned long long a,
                                                   unsigned long long b,
                                                   unsigned long long c) {
    unsigned long long d;
    asm("fma.rn.f32x2 %0, %1, %2, %3;" : "=l"(d) : "l"(a), "l"(b), "l"(c));
    return d;
}
__device__ __forceinline__ unsigned long long add2(unsigned long long a,
                                                   unsigned long long b) {
    unsigned long long d;
    asm("add.rn.f32x2 %0, %1, %2;" : "=l"(d) : "l"(a), "l"(b));
    return d;
}
__device__ __forceinline__ unsigned long long pk2(float x, float y) {
    unsigned long long d;
    asm("mov.b64 %0, {%1, %2};" : "=l"(d) : "f"(x), "f"(y));
    return d;
}
__device__ __forceinline__ float lo2(unsigned long long v) {
    return __uint_as_float((unsigned)(v & 0xffffffffu));
}
__device__ __forceinline__ float hi2(unsigned long long v) {
    return __uint_as_float((unsigned)(v >> 32));
}

// ---------------------------------------------------------------------------
// Kernel Z: zero the scatter targets every launch (graph replays reuse them)
// ---------------------------------------------------------------------------
__global__ void zero_kernel(const float* __restrict__ fc2_b) {
    int t = blockIdx.x * blockDim.x + threadIdx.x;
    if (t < FF) g_wF[t] = 0.0f;
    if (t == 0) g_c0 = fc2_b[0];
}

// ---------------------------------------------------------------------------
// Kernel T: tiled transpose x(B,F) -> g_xT(F,B). 32x32 tiles, 256 threads.
// ---------------------------------------------------------------------------
__global__ __launch_bounds__(256) void transpose_kernel(const float* __restrict__ x) {
    __shared__ float t[32][33];
    const int tx = threadIdx.x & 31;
    const int ty = threadIdx.x >> 5;          // 0..7
    const int col0 = blockIdx.x * 32;         // F dimension
    const int row0 = blockIdx.y * 32;         // B dimension
#pragma unroll
    for (int i = 0; i < 32; i += 8)
        t[ty + i][tx] = x[(size_t)(row0 + ty + i) * FF + col0 + tx];
    __syncthreads();
#pragma unroll
    for (int i = 0; i < 32; i += 8)
        g_xT[(size_t)(col0 + ty + i) * BB + row0 + tx] = t[tx][ty + i];
}

// ---------------------------------------------------------------------------
// Kernel A (v3): per-rule moments, COLUMN-PAIR-packed f32x2 FMAs.
// One warp = (rule, chunk); each lane processes 1 row per iteration via 16
// scalar LDGs (one 128B wavefront per column). g packed into 8 column pairs;
// each triangle row j uses aligned pairs:
//   j even: packed (j,k),(j,k+1) for k=j,j+2,..,14              (36 accs)
//   j odd : scalar diagonal (j,j), packed for k=j+1,j+3,..      (28 accs + 8)
// 64 packed + 8 scalar + 8 packed col-sums = ~190 regs, no spill.
// grid = NRULES, block = 128 (warp w handles chunk w).
// ---------------------------------------------------------------------------
__global__ __launch_bounds__(128, 1) void stats_kernel(const int* __restrict__ idx) {
    const int n     = blockIdx.x;
    const int chunk = threadIdx.x >> 5;
    const int lane  = threadIdx.x & 31;

    unsigned off[GG];                         // element offsets into g_xT
#pragma unroll
    for (int j = 0; j < GG; j++)
        off[j] = (unsigned)__ldg(idx + n * GG + j) * (unsigned)BB + chunk * RPC;

    unsigned long long accP[64];              // packed pair sums
    unsigned long long accS1[8];              // packed column sums
    float accD[8];                            // odd-j diagonals
#pragma unroll
    for (int i = 0; i < 64; i++) accP[i] = 0ull;
#pragma unroll
    for (int i = 0; i < 8; i++) { accS1[i] = 0ull; accD[i] = 0.0f; }

#pragma unroll 1
    for (int it = 0; it < RPC / 32; it++) {   // 64 iterations, 1 row/lane
        const int r = it * 32 + lane;
        float g[GG];
#pragma unroll
        for (int j = 0; j < GG; j++) g[j] = __ldg(g_xT + off[j] + r);

        unsigned long long gp[8];
#pragma unroll
        for (int m = 0; m < 8; m++) gp[m] = pk2(g[2 * m], g[2 * m + 1]);
#pragma unroll
        for (int m = 0; m < 8; m++) accS1[m] = add2(accS1[m], gp[m]);

        int pi = 0;
#pragma unroll
        for (int j = 0; j < GG; j++) {
            unsigned long long dup = pk2(g[j], g[j]);
            if (j & 1) accD[j >> 1] = fmaf(g[j], g[j], accD[j >> 1]);
            const int kstart = (j & 1) ? j + 1 : j;
#pragma unroll
            for (int k = kstart; k < GG; k += 2) {
                accP[pi] = fma2(dup, gp[k >> 1], accP[pi]);
                pi++;
            }
        }
    }

    // ---- epilogue: warp-reduce 152 stats, distribute stores over lanes ----
    float* dst = g_stats[n][chunk];

#pragma unroll
    for (int m = 0; m < 8; m++) {             // column sums (q = 2m, 2m+1)
        float vx = lo2(accS1[m]), vy = hi2(accS1[m]);
#pragma unroll
        for (int o = 16; o > 0; o >>= 1) {
            vx += __shfl_xor_sync(FULLMASK, vx, o);
            vy += __shfl_xor_sync(FULLMASK, vy, o);
        }
        if (lane == ((2 * m) & 31))     dst[2 * m]     = vx;
        if (lane == ((2 * m + 1) & 31)) dst[2 * m + 1] = vy;
    }
    {
        int pi = 0;
#pragma unroll
        for (int j = 0; j < GG; j++) {
            const int qrow = GG + j * GG - j * (j - 1) / 2 - j;  // q(j,k) = qrow + k
            if (j & 1) {
                float v = accD[j >> 1];
#pragma unroll
                for (int o = 16; o > 0; o >>= 1) v += __shfl_xor_sync(FULLMASK, v, o);
                const int q = qrow + j;
                if (lane == (q & 31)) dst[q] = v;
            }
            const int kstart = (j & 1) ? j + 1 : j;
#pragma unroll
            for (int k = kstart; k < GG; k += 2) {
                float vx = lo2(accP[pi]), vy = hi2(accP[pi]);
                pi++;
#pragma unroll
                for (int o = 16; o > 0; o >>= 1) {
                    vx += __shfl_xor_sync(FULLMASK, vx, o);
                    vy += __shfl_xor_sync(FULLMASK, vy, o);
                }
                const int q = qrow + k;
                if (lane == (q & 31))       dst[q]     = vx;
                if (lane == ((q + 1) & 31)) dst[q + 1] = vy;
            }
        }
    }
}

// ---------------------------------------------------------------------------
// Kernel B (v4): analytic BN fold, one warp per rule, LANE-PARALLEL varh.
// Lane j computes w_j^T C w_j independently (C broadcast from SMEM, no
// shuffle chains); caj/alpha exchanged via 16-float SMEM slots.
// block = 128 (4 warps = 4 rules), grid = NRULES/4.
// ---------------------------------------------------------------------------
__global__ __launch_bounds__(128) void fold_kernel(const int* __restrict__ idx,
                                                   const float* __restrict__ W1,
                                                   const float* __restrict__ bn1_w,
                                                   const float* __restrict__ W2,
                                                   const float* __restrict__ fc2_w) {
    __shared__ float sS[4][NSTAT];       // chunk-summed moments
    __shared__ float sC[4][GG][GG + 1];  // covariance (+1 pad)
    __shared__ float sW[4][GG][GG + 1];  // W1 rows (+1 pad)
    __shared__ float sCB[4][GG];         // W2[j]*bn1_w[j]
    __shared__ float sA[4][GG];          // caj
    __shared__ float sAl[4][GG];         // alpha

    const int w    = threadIdx.x >> 5;
    const int lane = threadIdx.x & 31;
    const int a    = lane & 15;                        // owned index (dup on hi half)
    const int n    = blockIdx.x * 4 + w;
    const float invB = 1.0f / (float)BB;

    // --- batched prefetch: W1 tile, combined scale, moment sums ---
    const float4* w4 = reinterpret_cast<const float4*>(W1 + (size_t)n * GG * GG);
#pragma unroll
    for (int i = lane; i < 64; i += 32) {
        float4 v = __ldg(w4 + i);
        int row = i >> 2, c = (i & 3) * 4;
        sW[w][row][c]     = v.x;
        sW[w][row][c + 1] = v.y;
        sW[w][row][c + 2] = v.z;
        sW[w][row][c + 3] = v.w;
    }
    if (lane < GG)
        sCB[w][lane] = __ldg(W2 + n * GG + lane) * __ldg(bn1_w + n * GG + lane);

    for (int q = lane; q < NSTAT; q += 32) {
        float acc = 0.0f;
#pragma unroll
        for (int c = 0; c < CHUNKS; c++) acc += g_stats[n][c][q];
        sS[w][q] = acc;
    }
    __syncwarp();

    // --- covariance into shared (lanes split the 136 pairs) ---
    {
        int p = 0;
#pragma unroll
        for (int j = 0; j < GG; j++) {
#pragma unroll
            for (int k = j; k < GG; k++) {
                if ((p & 31) == lane) {
                    float c = sS[w][GG + p] * invB
                            - (sS[w][j] * invB) * (sS[w][k] * invB);
                    sC[w][j][k] = c;
                    sC[w][k][j] = c;
                }
                p++;
            }
        }
    }
    __syncwarp();

    // --- lane j = a computes varh_j = w_j^T C w_j (no shuffles) ---
    float wreg[GG];
#pragma unroll
    for (int b = 0; b < GG; b++) wreg[b] = sW[w][a][b];   // stride-17: conflict-free
    float varh = 0.0f;
#pragma unroll
    for (int i = 0; i < GG; i++) {
        float t = 0.0f;
#pragma unroll
        for (int b = 0; b < GG; b++) t = fmaf(sC[w][i][b], wreg[b], t);  // broadcast
        varh = fmaf(wreg[i], t, varh);
    }
    float caj = sCB[w][a] * rsqrtf(varh + EPSV);
    if (lane < GG) sA[w][a] = caj;
    __syncwarp();

    // --- alpha_a = sum_j caj * W1[j][a] ---
    float alpha = 0.0f;
#pragma unroll
    for (int j = 0; j < GG; j++)
        alpha = fmaf(sA[w][j], sW[w][j][a], alpha);        // stride-1: conflict-free
    if (lane < GG) sAl[w][a] = alpha;
    __syncwarp();

    // --- varo = alpha^T C alpha ; muoa = alpha . mu ---
    float t2 = 0.0f;
#pragma unroll
    for (int b = 0; b < GG; b++) t2 = fmaf(sC[w][a][b], sAl[w][b], t2);
    float varo = alpha * t2;
    float muoa = alpha * (sS[w][a] * invB);
#pragma unroll
    for (int o = 8; o > 0; o >>= 1) {
        varo += __shfl_xor_sync(FULLMASK, varo, o);
        muoa += __shfl_xor_sync(FULLMASK, muoa, o);
    }
    float sc = __ldg(fc2_w + n) * rsqrtf(varo + EPSV);

    if (lane < GG) atomicAdd(&g_wF[__ldg(idx + n * GG + lane)], sc * alpha);
    if (lane == 0) atomicAdd(&g_c0, -sc * muoa);
}

// ---------------------------------------------------------------------------
// Kernel C: out[b] = x[b,:] . wF + c0   (8192x2048 GEMV)
// ---------------------------------------------------------------------------
__global__ __launch_bounds__(256) void gemv_kernel(const float* __restrict__ x,
                                                   float* __restrict__ out) {
    const int warp = threadIdx.x >> 5;
    const int lane = threadIdx.x & 31;
    const int row  = blockIdx.x * 8 + warp;

    const float4* xr = reinterpret_cast<const float4*>(x + (size_t)row * FF);
    const float4* wv = reinterpret_cast<const float4*>(g_wF);

    float acc = 0.0f;
#pragma unroll
    for (int i = 0; i < 16; i++) {
        float4 a = __ldg(xr + lane + 32 * i);
        float4 w = wv[lane + 32 * i];
        acc = fmaf(a.x, w.x, acc);
        acc = fmaf(a.y, w.y, acc);
        acc = fmaf(a.z, w.z, acc);
        acc = fmaf(a.w, w.w, acc);
    }
#pragma unroll
    for (int o = 16; o > 0; o >>= 1) acc += __shfl_xor_sync(FULLMASK, acc, o);
    if (lane == 0) out[row] = acc + g_c0;
}

// ---------------------------------------------------------------------------
extern "C" void kernel_launch(void* const* d_in, const int* in_sizes, int n_in,
                              void* d_out, int out_size) {
    const float* x     = (const float*)d_in[0];
    const int*   idx   = (const int*)  d_in[1];
    const float* W1    = (const float*)d_in[2];
    // d_in[3] = b1, d_in[5] = bn1_b, d_in[7] = b2 : cancel exactly under BN
    const float* bn1_w = (const float*)d_in[4];
    const float* W2    = (const float*)d_in[6];
    const float* fc2_w = (const float*)d_in[8];
    const float* fc2_b = (const float*)d_in[9];
    float* out = (float*)d_out;

    zero_kernel<<<(FF + 255) / 256, 256>>>(fc2_b);

    dim3 tgrid(FF / 32, BB / 32);
    transpose_kernel<<<tgrid, 256>>>(x);

    stats_kernel<<<NRULES, 128>>>(idx);

    fold_kernel<<<NRULES / 4, 128>>>(idx, W1, bn1_w, W2, fc2_w);

    gemv_kernel<<<BB / 8, 256>>>(x, out);
}

// round 9
// speedup vs baseline: 1.1975x; 1.1975x over previous
#include <cuda_runtime.h>
#include <cuda_bf16.h>

#define BB      8192
#define FF      2048
#define NRULES  512
#define GG      16
#define NSTAT   152          // 16 sums + 136 pair-products
#define CHUNKS  8
#define RPC     (BB / CHUNKS)   // 1024 rows per chunk
#define TROWS   64              // rows per smem tile
#define EPSV    1e-5f
#define FULLMASK 0xffffffffu

typedef unsigned long long ull;

// Scratch (device globals: allocation-free per harness rules)
__device__ float g_xT[(size_t)FF * BB];            // 64MB transposed x
__device__ float g_stats[NRULES][CHUNKS][NSTAT];   // partial moments
__device__ __align__(16) float g_wF[FF];           // folded GEMV weights
__device__ float g_c0;                             // folded constant

// ---------------------------------------------------------------------------
// packed f32x2 helpers (sm_103a)
// ---------------------------------------------------------------------------
__device__ __forceinline__ ull fma2(ull a, ull b, ull c) {
    ull d;
    asm("fma.rn.f32x2 %0, %1, %2, %3;" : "=l"(d) : "l"(a), "l"(b), "l"(c));
    return d;
}
__device__ __forceinline__ ull add2(ull a, ull b) {
    ull d;
    asm("add.rn.f32x2 %0, %1, %2;" : "=l"(d) : "l"(a), "l"(b));
    return d;
}
__device__ __forceinline__ float pairsum(ull v) {
    return __uint_as_float((unsigned)(v & 0xffffffffu)) +
           __uint_as_float((unsigned)(v >> 32));
}

// ---------------------------------------------------------------------------
// Kernel Z: zero the scatter targets every launch (graph replays reuse them)
// ---------------------------------------------------------------------------
__global__ void zero_kernel(const float* __restrict__ fc2_b) {
    int t = blockIdx.x * blockDim.x + threadIdx.x;
    if (t < FF) g_wF[t] = 0.0f;
    if (t == 0) g_c0 = fc2_b[0];
}

// ---------------------------------------------------------------------------
// Kernel T: tiled transpose x(B,F) -> g_xT(F,B). 32x32 tiles, 256 threads.
// ---------------------------------------------------------------------------
__global__ __launch_bounds__(256) void transpose_kernel(const float* __restrict__ x) {
    __shared__ float t[32][33];
    const int tx = threadIdx.x & 31;
    const int ty = threadIdx.x >> 5;          // 0..7
    const int col0 = blockIdx.x * 32;         // F dimension
    const int row0 = blockIdx.y * 32;         // B dimension
#pragma unroll
    for (int i = 0; i < 32; i += 8)
        t[ty + i][tx] = x[(size_t)(row0 + ty + i) * FF + col0 + tx];
    __syncthreads();
#pragma unroll
    for (int i = 0; i < 32; i += 8)
        g_xT[(size_t)(col0 + ty + i) * BB + row0 + tx] = t[tx][ty + i];
}

// ---------------------------------------------------------------------------
// Kernel A (v4): per-rule moments, WARP-PARTITIONED product matrix.
// One warp = (rule, chunk). Thread (tj = lane>>3, tk = lane&7) owns the
// 4x2 block rows {4tj..4tj+3} x cols {2tk,2tk+1} of the FULL 16x16 product
// matrix -> only 8 packed accumulators per thread (~45 regs, NO SPILLS).
// Rows staged through a per-warp smem tile (TROWS x 16, stride 66 floats ->
// conflict-free LDS.64); products accumulated 2 rows at a time via f32x2.
// Epilogue: each (j,k) has a unique owner -> direct scattered stores,
// no shuffles. First moments: every thread sums its a-block; tk==0 stores.
// grid = (NRULES, CHUNKS/4), block = 128 (warp w handles chunk-sub w).
// ---------------------------------------------------------------------------
__global__ __launch_bounds__(128) void stats_kernel(const int* __restrict__ idx) {
    __shared__ float sT[4][GG][TROWS + 2];    // +2 pad: 8B align + bank spread

    const int w     = threadIdx.x >> 5;
    const int lane  = threadIdx.x & 31;
    const int n     = blockIdx.x;
    const int chunk = blockIdx.y * 4 + w;
    const int tj    = lane >> 3;              // 0..3 -> j rows 4tj..4tj+3
    const int tk    = lane & 7;               // 0..7 -> k cols 2tk,2tk+1

    unsigned off[GG];
#pragma unroll
    for (int j = 0; j < GG; j++)
        off[j] = (unsigned)__ldg(idx + n * GG + j) * (unsigned)BB + chunk * RPC;

    ull acc[4][2];                            // packed over row-pairs
    ull s1p[4];                               // packed column sums (a-block)
#pragma unroll
    for (int a = 0; a < 4; a++) {
        acc[a][0] = 0ull; acc[a][1] = 0ull; s1p[a] = 0ull;
    }

#pragma unroll 1
    for (int tile = 0; tile < RPC / TROWS; tile++) {   // 16 tiles
        const int r0 = tile * TROWS;
        __syncwarp();                                  // WAR: tile reuse
#pragma unroll
        for (int j = 0; j < GG; j++) {
            ull v = __ldg(reinterpret_cast<const ull*>(g_xT + off[j] + r0 + 2 * lane));
            *reinterpret_cast<ull*>(&sT[w][j][2 * lane]) = v;
        }
        __syncwarp();

#pragma unroll 8
        for (int r = 0; r < TROWS; r += 2) {
            ull a0 = *reinterpret_cast<const ull*>(&sT[w][4 * tj + 0][r]);
            ull a1 = *reinterpret_cast<const ull*>(&sT[w][4 * tj + 1][r]);
            ull a2 = *reinterpret_cast<const ull*>(&sT[w][4 * tj + 2][r]);
            ull a3 = *reinterpret_cast<const ull*>(&sT[w][4 * tj + 3][r]);
            ull b0 = *reinterpret_cast<const ull*>(&sT[w][2 * tk + 0][r]);
            ull b1 = *reinterpret_cast<const ull*>(&sT[w][2 * tk + 1][r]);

            acc[0][0] = fma2(a0, b0, acc[0][0]);
            acc[0][1] = fma2(a0, b1, acc[0][1]);
            acc[1][0] = fma2(a1, b0, acc[1][0]);
            acc[1][1] = fma2(a1, b1, acc[1][1]);
            acc[2][0] = fma2(a2, b0, acc[2][0]);
            acc[2][1] = fma2(a2, b1, acc[2][1]);
            acc[3][0] = fma2(a3, b0, acc[3][0]);
            acc[3][1] = fma2(a3, b1, acc[3][1]);

            s1p[0] = add2(s1p[0], a0);
            s1p[1] = add2(s1p[1], a1);
            s1p[2] = add2(s1p[2], a2);
            s1p[3] = add2(s1p[3], a3);
        }
    }

    // ---- epilogue: unique owner per (j,k) -> direct stores, no shuffles ----
    float* dst = g_stats[n][chunk];
#pragma unroll
    for (int j2 = 0; j2 < 4; j2++) {
#pragma unroll
        for (int k2 = 0; k2 < 2; k2++) {
            const int j = 4 * tj + j2;
            const int k = 2 * tk + k2;
            if (j <= k) {
                const int q = GG + j * GG - j * (j - 1) / 2 + (k - j);
                dst[q] = pairsum(acc[j2][k2]);
            }
        }
    }
    if (tk == 0) {
#pragma unroll
        for (int j2 = 0; j2 < 4; j2++)
            dst[4 * tj + j2] = pairsum(s1p[j2]);
    }
}

// ---------------------------------------------------------------------------
// Kernel B (v4): analytic BN fold, one warp per rule, LANE-PARALLEL varh.
// block = 128 (4 warps = 4 rules), grid = NRULES/4.
// ---------------------------------------------------------------------------
__global__ __launch_bounds__(128) void fold_kernel(const int* __restrict__ idx,
                                                   const float* __restrict__ W1,
                                                   const float* __restrict__ bn1_w,
                                                   const float* __restrict__ W2,
                                                   const float* __restrict__ fc2_w) {
    __shared__ float sS[4][NSTAT];       // chunk-summed moments
    __shared__ float sC[4][GG][GG + 1];  // covariance (+1 pad)
    __shared__ float sW[4][GG][GG + 1];  // W1 rows (+1 pad)
    __shared__ float sCB[4][GG];         // W2[j]*bn1_w[j]
    __shared__ float sA[4][GG];          // caj
    __shared__ float sAl[4][GG];         // alpha

    const int w    = threadIdx.x >> 5;
    const int lane = threadIdx.x & 31;
    const int a    = lane & 15;                        // owned index (dup on hi half)
    const int n    = blockIdx.x * 4 + w;
    const float invB = 1.0f / (float)BB;

    // --- batched prefetch: W1 tile, combined scale, moment sums ---
    const float4* w4 = reinterpret_cast<const float4*>(W1 + (size_t)n * GG * GG);
#pragma unroll
    for (int i = lane; i < 64; i += 32) {
        float4 v = __ldg(w4 + i);
        int row = i >> 2, c = (i & 3) * 4;
        sW[w][row][c]     = v.x;
        sW[w][row][c + 1] = v.y;
        sW[w][row][c + 2] = v.z;
        sW[w][row][c + 3] = v.w;
    }
    if (lane < GG)
        sCB[w][lane] = __ldg(W2 + n * GG + lane) * __ldg(bn1_w + n * GG + lane);

    for (int q = lane; q < NSTAT; q += 32) {
        float acc = 0.0f;
#pragma unroll
        for (int c = 0; c < CHUNKS; c++) acc += g_stats[n][c][q];
        sS[w][q] = acc;
    }
    __syncwarp();

    // --- covariance into shared (lanes split the 136 pairs) ---
    {
        int p = 0;
#pragma unroll
        for (int j = 0; j < GG; j++) {
#pragma unroll
            for (int k = j; k < GG; k++) {
                if ((p & 31) == lane) {
                    float c = sS[w][GG + p] * invB
                            - (sS[w][j] * invB) * (sS[w][k] * invB);
                    sC[w][j][k] = c;
                    sC[w][k][j] = c;
                }
                p++;
            }
        }
    }
    __syncwarp();

    // --- lane j = a computes varh_j = w_j^T C w_j (no shuffles) ---
    float wreg[GG];
#pragma unroll
    for (int b = 0; b < GG; b++) wreg[b] = sW[w][a][b];
    float varh = 0.0f;
#pragma unroll
    for (int i = 0; i < GG; i++) {
        float t = 0.0f;
#pragma unroll
        for (int b = 0; b < GG; b++) t = fmaf(sC[w][i][b], wreg[b], t);  // broadcast
        varh = fmaf(wreg[i], t, varh);
    }
    float caj = sCB[w][a] * rsqrtf(varh + EPSV);
    if (lane < GG) sA[w][a] = caj;
    __syncwarp();

    // --- alpha_a = sum_j caj * W1[j][a] ---
    float alpha = 0.0f;
#pragma unroll
    for (int j = 0; j < GG; j++)
        alpha = fmaf(sA[w][j], sW[w][j][a], alpha);
    if (lane < GG) sAl[w][a] = alpha;
    __syncwarp();

    // --- varo = alpha^T C alpha ; muoa = alpha . mu ---
    float t2 = 0.0f;
#pragma unroll
    for (int b = 0; b < GG; b++) t2 = fmaf(sC[w][a][b], sAl[w][b], t2);
    float varo = alpha * t2;
    float muoa = alpha * (sS[w][a] * invB);
#pragma unroll
    for (int o = 8; o > 0; o >>= 1) {
        varo += __shfl_xor_sync(FULLMASK, varo, o);
        muoa += __shfl_xor_sync(FULLMASK, muoa, o);
    }
    float sc = __ldg(fc2_w + n) * rsqrtf(varo + EPSV);

    if (lane < GG) atomicAdd(&g_wF[__ldg(idx + n * GG + lane)], sc * alpha);
    if (lane == 0) atomicAdd(&g_c0, -sc * muoa);
}

// ---------------------------------------------------------------------------
// Kernel C: out[b] = x[b,:] . wF + c0   (8192x2048 GEMV)
// ---------------------------------------------------------------------------
__global__ __launch_bounds__(256) void gemv_kernel(const float* __restrict__ x,
                                                   float* __restrict__ out) {
    const int warp = threadIdx.x >> 5;
    const int lane = threadIdx.x & 31;
    const int row  = blockIdx.x * 8 + warp;

    const float4* xr = reinterpret_cast<const float4*>(x + (size_t)row * FF);
    const float4* wv = reinterpret_cast<const float4*>(g_wF);

    float acc = 0.0f;
#pragma unroll
    for (int i = 0; i < 16; i++) {
        float4 a = __ldg(xr + lane + 32 * i);
        float4 w = wv[lane + 32 * i];
        acc = fmaf(a.x, w.x, acc);
        acc = fmaf(a.y, w.y, acc);
        acc = fmaf(a.z, w.z, acc);
        acc = fmaf(a.w, w.w, acc);
    }
#pragma unroll
    for (int o = 16; o > 0; o >>= 1) acc += __shfl_xor_sync(FULLMASK, acc, o);
    if (lane == 0) out[row] = acc + g_c0;
}

// ---------------------------------------------------------------------------
extern "C" void kernel_launch(void* const* d_in, const int* in_sizes, int n_in,
                              void* d_out, int out_size) {
    const float* x     = (const float*)d_in[0];
    const int*   idx   = (const int*)  d_in[1];
    const float* W1    = (const float*)d_in[2];
    // d_in[3] = b1, d_in[5] = bn1_b, d_in[7] = b2 : cancel exactly under BN
    const float* bn1_w = (const float*)d_in[4];
    const float* W2    = (const float*)d_in[6];
    const float* fc2_w = (const float*)d_in[8];
    const float* fc2_b = (const float*)d_in[9];
    float* out = (float*)d_out;

    zero_kernel<<<(FF + 255) / 256, 256>>>(fc2_b);

    dim3 tgrid(FF / 32, BB / 32);
    transpose_kernel<<<tgrid, 256>>>(x);

    dim3 sgrid(NRULES, CHUNKS / 4);
    stats_kernel<<<sgrid, 128>>>(idx);

    fold_kernel<<<NRULES / 4, 128>>>(idx, W1, bn1_w, W2, fc2_w);

    gemv_kernel<<<BB / 8, 256>>>(x, out);
}

// round 14
// speedup vs baseline: 1.7815x; 1.4877x over previous
#include <cuda_runtime.h>
#include <cuda_bf16.h>
#include <cstdint>

#define BB      8192
#define FF      2048
#define NRULES  512
#define GG      16
#define NPAIR   136
#define EPSV    1e-5f
#define FULLMASK 0xffffffffu

#define NCHUNK   4
#define KC       (BB / NCHUNK)    // 2048 rows per (rule,chunk) warp
#define KTILE    64               // bf16 k per smem tile
#define NT       (KC / KTILE)     // 32 tiles per warp
#define ROWSTRIDE 72              // bf16 per smem row (144B): conflict-free

// Scratch (device globals: allocation-free per harness rules)
__device__ __nv_bfloat16 g_xTh[(size_t)FF * BB];     // 32MB transposed bf16 x
__device__ float g_colsum[FF];                       // per-feature sums (fp32)
__device__ float g_pair[NRULES][NCHUNK][NPAIR];      // per-rule pair products
__device__ __align__(16) float g_wF[FF];             // folded GEMV weights
__device__ float g_c0;                               // folded constant

// ---------------------------------------------------------------------------
// warp-MMA helpers (plain sm_80+ PTX: compiles on compute_103, no 'a' needed)
// ---------------------------------------------------------------------------
__device__ __forceinline__ unsigned smem_u32(const void* p) {
    unsigned a;
    asm("{ .reg .u64 t; cvta.to.shared.u64 t, %1; cvt.u32.u64 %0, t; }"
        : "=r"(a) : "l"(p));
    return a;
}
__device__ __forceinline__ void ldsm_x4(unsigned& r0, unsigned& r1,
                                        unsigned& r2, unsigned& r3, unsigned addr) {
    asm volatile("ldmatrix.sync.aligned.m8n8.x4.shared.b16 {%0,%1,%2,%3}, [%4];"
                 : "=r"(r0), "=r"(r1), "=r"(r2), "=r"(r3) : "r"(addr));
}
__device__ __forceinline__ void ldsm_x2(unsigned& r0, unsigned& r1, unsigned addr) {
    asm volatile("ldmatrix.sync.aligned.m8n8.x2.shared.b16 {%0,%1}, [%2];"
                 : "=r"(r0), "=r"(r1) : "r"(addr));
}
__device__ __forceinline__ void mma16816(float* d, unsigned a0, unsigned a1,
                                         unsigned a2, unsigned a3,
                                         unsigned b0, unsigned b1) {
    asm volatile(
        "mma.sync.aligned.m16n8k16.row.col.f32.bf16.bf16.f32 "
        "{%0,%1,%2,%3}, {%4,%5,%6,%7}, {%8,%9}, {%0,%1,%2,%3};"
        : "+f"(d[0]), "+f"(d[1]), "+f"(d[2]), "+f"(d[3])
        : "r"(a0), "r"(a1), "r"(a2), "r"(a3), "r"(b0), "r"(b1));
}

// ---------------------------------------------------------------------------
// Kernel Z: zero scatter targets every launch (graph replays reuse them)
// ---------------------------------------------------------------------------
__global__ void zero_kernel(const float* __restrict__ fc2_b) {
    int t = blockIdx.x * blockDim.x + threadIdx.x;
    if (t < FF) { g_wF[t] = 0.0f; g_colsum[t] = 0.0f; }
    if (t == 0) g_c0 = fc2_b[0];
}

// ---------------------------------------------------------------------------
// Kernel T: transpose + bf16 convert + column sums.  (FIXED write phase)
// Load: t[b_local][f_local]. Write: warp ty emits features 4ty..4ty+3;
// lane l reads t[l][fc] (banks (l+fc)&31: conflict-free) and stores one
// bf16 at batch row0+l. Colsum reduced over the 32 batch values.
// ---------------------------------------------------------------------------
__global__ __launch_bounds__(256) void transpose_cvt_kernel(const float* __restrict__ x) {
    __shared__ float t[32][33];
    const int lane = threadIdx.x & 31;
    const int ty   = threadIdx.x >> 5;        // 0..7
    const int col0 = blockIdx.x * 32;         // F dimension
    const int row0 = blockIdx.y * 32;         // B dimension
#pragma unroll
    for (int i = 0; i < 32; i += 8)
        t[ty + i][lane] = x[(size_t)(row0 + ty + i) * FF + col0 + lane];
    __syncthreads();
#pragma unroll
    for (int c = 0; c < 4; c++) {
        const int fc = 4 * ty + c;            // local feature
        float v = t[lane][fc];                // batch = lane
        g_xTh[(size_t)(col0 + fc) * BB + row0 + lane] = __float2bfloat16(v);
        float s = v;
#pragma unroll
        for (int o = 16; o > 0; o >>= 1) s += __shfl_xor_sync(FULLMASK, s, o);
        if (lane == 0) atomicAdd(&g_colsum[col0 + fc], s);
    }
}

// ---------------------------------------------------------------------------
// Kernel A (v6): warp-level bf16 tensor-core syrk for pair moments.
// One warp = (rule n, K-chunk kc). G = 16 gathered columns x KC rows (k-contig
// after transpose). Per 16x64 smem tile: 4 K=16 slabs, each A=ldmatrix.x4,
// B(n-half)=ldmatrix.x2 (row.col mma wants B as n x k = our layout), 2 MMAs.
// f32 accumulator frags; unique-owner triangle stores, no shuffles.
// block = 128 (4 warps), grid = NRULES*NCHUNK/4 = 512.
// ---------------------------------------------------------------------------
__global__ __launch_bounds__(128) void stats_mma_kernel(const int* __restrict__ idx) {
    __shared__ __align__(16) __nv_bfloat16 sT[4][GG][ROWSTRIDE];

    const int wid  = threadIdx.x >> 5;
    const int lane = threadIdx.x & 31;
    const int wg   = blockIdx.x * 4 + wid;
    const int n    = wg >> 2;                 // rule
    const int kc   = wg & 3;                  // K chunk

    // staging map: unit t = lane + 32*i -> row t>>3, 16B-unit t&7
    const __nv_bfloat16* srcp[4];
    __nv_bfloat16* stp[4];
#pragma unroll
    for (int i = 0; i < 4; i++) {
        const int t   = lane + 32 * i;
        const int row = t >> 3, un = t & 7;
        srcp[i] = g_xTh + (size_t)__ldg(idx + n * GG + row) * BB + kc * KC + un * 8;
        stp[i]  = &sT[wid][row][un * 8];
    }

    const unsigned sbase = smem_u32(&sT[wid][0][0]);
    // ldmatrix address components (bytes; row stride 144)
    const unsigned arow  = (lane & 7) + ((lane >> 3) & 1) * 8;
    const unsigned aoff  = arow * 144u + ((lane >> 4) & 1) * 16u;
    const unsigned brow  = (lane & 7);
    const unsigned bko   = ((lane >> 3) & 1) * 16u;

    float d[2][4];
#pragma unroll
    for (int h = 0; h < 2; h++)
#pragma unroll
        for (int e = 0; e < 4; e++) d[h][e] = 0.0f;

    uint4 v[4];
#pragma unroll
    for (int i = 0; i < 4; i++) v[i] = __ldg(reinterpret_cast<const uint4*>(srcp[i]));

#pragma unroll 1
    for (int kt = 0; kt < NT; kt++) {
        __syncwarp();
#pragma unroll
        for (int i = 0; i < 4; i++) *reinterpret_cast<uint4*>(stp[i]) = v[i];
        __syncwarp();
        if (kt + 1 < NT) {
#pragma unroll
            for (int i = 0; i < 4; i++)
                v[i] = __ldg(reinterpret_cast<const uint4*>(srcp[i] + (kt + 1) * KTILE));
        }
#pragma unroll
        for (int s = 0; s < 4; s++) {
            unsigned a0, a1, a2, a3, b0, b1;
            ldsm_x4(a0, a1, a2, a3, sbase + aoff + s * 32u);
            ldsm_x2(b0, b1, sbase + brow * 144u + bko + s * 32u);           // n 0..7
            mma16816(d[0], a0, a1, a2, a3, b0, b1);
            ldsm_x2(b0, b1, sbase + (8 + brow) * 144u + bko + s * 32u);     // n 8..15
            mma16816(d[1], a0, a1, a2, a3, b0, b1);
        }
    }

    // epilogue: unique owner per (j,k) -> direct triangle stores
    const int gid = lane >> 2, tig = lane & 3;
    float* dst = g_pair[n][kc];
#pragma unroll
    for (int h = 0; h < 2; h++) {
#pragma unroll
        for (int e = 0; e < 4; e++) {
            const int j = gid + (e >> 1) * 8;
            const int k = h * 8 + tig * 2 + (e & 1);
            if (j <= k)
                dst[16 * j - j * (j - 1) / 2 + (k - j)] = d[h][e];
        }
    }
}

// ---------------------------------------------------------------------------
// Kernel B: analytic BN fold, one warp per rule, lane-parallel varh.
// mu from g_colsum (no gather); pairs from g_pair (NCHUNK summed).
// block = 128 (4 warps = 4 rules), grid = NRULES/4.
// ---------------------------------------------------------------------------
__global__ __launch_bounds__(128) void fold_kernel(const int* __restrict__ idx,
                                                   const float* __restrict__ W1,
                                                   const float* __restrict__ bn1_w,
                                                   const float* __restrict__ W2,
                                                   const float* __restrict__ fc2_w) {
    __shared__ float sP[4][NPAIR];
    __shared__ float sMu[4][GG];
    __shared__ float sC[4][GG][GG + 1];
    __shared__ float sW[4][GG][GG + 1];
    __shared__ float sCB[4][GG];
    __shared__ float sA[4][GG];
    __shared__ float sAl[4][GG];

    const int w    = threadIdx.x >> 5;
    const int lane = threadIdx.x & 31;
    const int a    = lane & 15;
    const int n    = blockIdx.x * 4 + w;
    const float invB = 1.0f / (float)BB;

    const float4* w4 = reinterpret_cast<const float4*>(W1 + (size_t)n * GG * GG);
#pragma unroll
    for (int i = lane; i < 64; i += 32) {
        float4 v = __ldg(w4 + i);
        int row = i >> 2, c = (i & 3) * 4;
        sW[w][row][c]     = v.x;
        sW[w][row][c + 1] = v.y;
        sW[w][row][c + 2] = v.z;
        sW[w][row][c + 3] = v.w;
    }
    if (lane < GG) {
        sCB[w][lane] = __ldg(W2 + n * GG + lane) * __ldg(bn1_w + n * GG + lane);
        sMu[w][lane] = g_colsum[__ldg(idx + n * GG + lane)] * invB;
    }
    for (int q = lane; q < NPAIR; q += 32) {
        float acc = 0.0f;
#pragma unroll
        for (int c = 0; c < NCHUNK; c++) acc += g_pair[n][c][q];
        sP[w][q] = acc;
    }
    __syncwarp();

    // covariance
    {
        int p = 0;
#pragma unroll
        for (int j = 0; j < GG; j++) {
#pragma unroll
            for (int k = j; k < GG; k++) {
                if ((p & 31) == lane) {
                    float c = sP[w][p] * invB - sMu[w][j] * sMu[w][k];
                    sC[w][j][k] = c;
                    sC[w][k][j] = c;
                }
                p++;
            }
        }
    }
    __syncwarp();

    // lane a: varh_a = w_a^T C w_a
    float wreg[GG];
#pragma unroll
    for (int b = 0; b < GG; b++) wreg[b] = sW[w][a][b];
    float varh = 0.0f;
#pragma unroll
    for (int i = 0; i < GG; i++) {
        float t = 0.0f;
#pragma unroll
        for (int b = 0; b < GG; b++) t = fmaf(sC[w][i][b], wreg[b], t);
        varh = fmaf(wreg[i], t, varh);
    }
    float caj = sCB[w][a] * rsqrtf(varh + EPSV);
    if (lane < GG) sA[w][a] = caj;
    __syncwarp();

    float alpha = 0.0f;
#pragma unroll
    for (int j = 0; j < GG; j++)
        alpha = fmaf(sA[w][j], sW[w][j][a], alpha);
    if (lane < GG) sAl[w][a] = alpha;
    __syncwarp();

    float t2 = 0.0f;
#pragma unroll
    for (int b = 0; b < GG; b++) t2 = fmaf(sC[w][a][b], sAl[w][b], t2);
    float varo = alpha * t2;
    float muoa = alpha * sMu[w][a];
#pragma unroll
    for (int o = 8; o > 0; o >>= 1) {
        varo += __shfl_xor_sync(FULLMASK, varo, o);
        muoa += __shfl_xor_sync(FULLMASK, muoa, o);
    }
    float sc = __ldg(fc2_w + n) * rsqrtf(varo + EPSV);

    if (lane < GG) atomicAdd(&g_wF[__ldg(idx + n * GG + lane)], sc * alpha);
    if (lane == 0) atomicAdd(&g_c0, -sc * muoa);
}

// ---------------------------------------------------------------------------
// Kernel C: out[b] = x[b,:] . wF + c0   (8192x2048 GEMV)
// ---------------------------------------------------------------------------
__global__ __launch_bounds__(256) void gemv_kernel(const float* __restrict__ x,
                                                   float* __restrict__ out) {
    const int warp = threadIdx.x >> 5;
    const int lane = threadIdx.x & 31;
    const int row  = blockIdx.x * 8 + warp;

    const float4* xr = reinterpret_cast<const float4*>(x + (size_t)row * FF);
    const float4* wv = reinterpret_cast<const float4*>(g_wF);

    float acc = 0.0f;
#pragma unroll
    for (int i = 0; i < 16; i++) {
        float4 a = __ldg(xr + lane + 32 * i);
        float4 w = wv[lane + 32 * i];
        acc = fmaf(a.x, w.x, acc);
        acc = fmaf(a.y, w.y, acc);
        acc = fmaf(a.z, w.z, acc);
        acc = fmaf(a.w, w.w, acc);
    }
#pragma unroll
    for (int o = 16; o > 0; o >>= 1) acc += __shfl_xor_sync(FULLMASK, acc, o);
    if (lane == 0) out[row] = acc + g_c0;
}

// ---------------------------------------------------------------------------
extern "C" void kernel_launch(void* const* d_in, const int* in_sizes, int n_in,
                              void* d_out, int out_size) {
    const float* x     = (const float*)d_in[0];
    const int*   idx   = (const int*)  d_in[1];
    const float* W1    = (const float*)d_in[2];
    // d_in[3] = b1, d_in[5] = bn1_b, d_in[7] = b2 : cancel exactly under BN
    const float* bn1_w = (const float*)d_in[4];
    const float* W2    = (const float*)d_in[6];
    const float* fc2_w = (const float*)d_in[8];
    const float* fc2_b = (const float*)d_in[9];
    float* out = (float*)d_out;

    zero_kernel<<<(FF + 255) / 256, 256>>>(fc2_b);

    dim3 tgrid(FF / 32, BB / 32);
    transpose_cvt_kernel<<<tgrid, 256>>>(x);

    stats_mma_kernel<<<NRULES * NCHUNK / 4, 128>>>(idx);

    fold_kernel<<<NRULES / 4, 128>>>(idx, W1, bn1_w, W2, fc2_w);

    gemv_kernel<<<BB / 8, 256>>>(x, out);
}